// round 2
// baseline (speedup 1.0000x reference)
#include <cuda_runtime.h>
#include <cuda_bf16.h>

// PCEN: out = (E / (eps + M)^alpha + delta)^r - delta^r
// with causal EMA M_t = (1-s) M_{t-1} + s E_t, per (B,C) row over T.
//
// One block per row (B*C = 5120 rows), 256 threads, 16 elems/thread.
// Linear-recurrence parallel scan: thread-local scan -> warp shuffle scan
// with ratio A = a^16 -> serial 8-warp carry (ratio A^32) -> recompute.
// Global I/O staged through padded smem (stride 17 per 16-chunk: scan-phase
// LDS is bank-conflict-free) with float4 LDG/STG for 4x fewer memory insts.

#define T_LEN   4000
#define THREADS 256
#define CHUNK   16
#define NCHUNK  (T_LEN / CHUNK)   // 250
#define NVEC4   (T_LEN / 4)       // 1000
#define EPS     1e-6f

// padded smem: element i lives at i + (i>>4)
#define PADDED_SZ (T_LEN + NCHUNK)  // 4250 floats

__global__ __launch_bounds__(THREADS, 4)
void pcen_kernel(const float* __restrict__ E,
                 const float* __restrict__ log_alpha,
                 const float* __restrict__ log_delta,
                 const float* __restrict__ log_r,
                 const float* __restrict__ log_s,
                 float* __restrict__ out,
                 int C)
{
    __shared__ float buf[PADDED_SZ];
    __shared__ float warp_sum[THREADS / 32];
    __shared__ float warp_pref[THREADS / 32];

    const int row = blockIdx.x;            // b*C + c
    const int c   = row % C;
    const float4* e4 = (const float4*)(E   + (size_t)row * T_LEN);
    float4*       o4 = (float4*)      (out + (size_t)row * T_LEN);

    const int tid  = threadIdx.x;
    const int lane = tid & 31;
    const int wid  = tid >> 5;

    // --- per-channel params (redundant per thread; cheap) ---
    const float s     = 1.0f / (1.0f + __expf(-__ldg(&log_s[c])));
    const float a     = 1.0f - s;
    const float alpha = 1.0f / (1.0f + __expf(-__ldg(&log_alpha[c])));
    const float delta = __logf(1.0f + __expf(__ldg(&log_delta[c])));
    const float r     = 1.0f / (1.0f + __expf(-__ldg(&log_r[c])));
    const float dr    = __powf(delta, r);

    // --- coalesced float4 load into padded smem ---
    // A float4 covers elements [4j, 4j+3], all inside one 16-chunk, so the
    // padded indices are contiguous: idx = 4j + (4j>>4), then +1,+2,+3.
    #pragma unroll 2
    for (int j = tid; j < NVEC4; j += THREADS) {
        float4 v = __ldg(&e4[j]);
        int i = 4 * j;
        int idx = i + (i >> 4);
        buf[idx + 0] = v.x;
        buf[idx + 1] = v.y;
        buf[idx + 2] = v.z;
        buf[idx + 3] = v.w;
    }
    __syncthreads();

    // --- pass 1: thread-local scan over its 16-chunk (conflict-free LDS) ---
    float ev[CHUNK];
    float local = 0.0f;
    const int base = tid * (CHUNK + 1);   // = tid*17
    if (tid < NCHUNK) {
        #pragma unroll
        for (int k = 0; k < CHUNK; k++) {
            ev[k] = buf[base + k];
            local = a * local + s * ev[k];
        }
    }

    // A = a^16 (chunk ratio)
    float A = a * a;          // a^2
    A = A * A;                // a^4
    A = A * A;                // a^8
    A = A * A;                // a^16

    // --- warp Hillis-Steele scan of p_i = A * p_{i-1} + local_i ---
    // Apow = A^lane built from the doubling w for free.
    float p = local;
    float w = A;              // A^(2^k)
    float Apow = 1.0f;        // A^lane
    #pragma unroll
    for (int d = 1; d < 32; d <<= 1) {
        float up = __shfl_up_sync(0xffffffffu, p, d);
        if (lane >= d) p += w * up;
        if (lane & d)  Apow *= w;
        w = w * w;
    }
    const float A32 = w;      // A^32

    // exclusive prefix within warp
    float pe = __shfl_up_sync(0xffffffffu, p, 1);
    if (lane == 0) pe = 0.0f;

    if (lane == 31) warp_sum[wid] = p;
    __syncthreads();

    // serial carry across the 8 warps (ratio A32), exclusive
    if (tid == 0) {
        float acc = 0.0f;
        #pragma unroll
        for (int j = 0; j < THREADS / 32; j++) {
            warp_pref[j] = acc;
            acc = A32 * acc + warp_sum[j];
        }
    }
    __syncthreads();

    // --- pass 2: recompute with true incoming state, apply PCEN math ---
    if (tid < NCHUNK) {
        float m = Apow * warp_pref[wid] + pe;   // M state before this chunk
        #pragma unroll
        for (int k = 0; k < CHUNK; k++) {
            m = a * m + s * ev[k];
            float x  = EPS + m;
            float pw = __powf(x, -alpha);        // x^{-alpha}: LG2+EX2
            float u  = ev[k] * pw + delta;
            float y  = __powf(u, r) - dr;        // u^r: LG2+EX2
            buf[base + k] = y;
        }
    }
    __syncthreads();

    // --- coalesced float4 store ---
    #pragma unroll 2
    for (int j = tid; j < NVEC4; j += THREADS) {
        int i = 4 * j;
        int idx = i + (i >> 4);
        float4 v;
        v.x = buf[idx + 0];
        v.y = buf[idx + 1];
        v.z = buf[idx + 2];
        v.w = buf[idx + 3];
        o4[j] = v;
    }
}

extern "C" void kernel_launch(void* const* d_in, const int* in_sizes, int n_in,
                              void* d_out, int out_size)
{
    const float* E         = (const float*)d_in[0];
    const float* log_alpha = (const float*)d_in[1];
    const float* log_delta = (const float*)d_in[2];
    const float* log_r     = (const float*)d_in[3];
    const float* log_s     = (const float*)d_in[4];
    float*       out       = (float*)d_out;

    const int C    = in_sizes[1];
    const int rows = in_sizes[0] / T_LEN;   // B*C

    pcen_kernel<<<rows, THREADS>>>(E, log_alpha, log_delta, log_r, log_s, out, C);
}

// round 5
// speedup vs baseline: 1.0762x; 1.0762x over previous
#include <cuda_runtime.h>
#include <cuda_bf16.h>

// PCEN: out = (E / (eps + M)^alpha + delta)^r - delta^r
// with causal EMA M_t = (1-s) M_{t-1} + s E_t, per (B,C) row over T.
//
// One block per row (B*C = 5120 rows), 256 threads, 16 elems/thread.
// Linear-recurrence parallel scan: thread-local scan -> warp shuffle scan
// (ratio A = a^16) -> serial 8-warp carry (ratio A^32) -> recompute.
//
// Smem layout: each 16-elem chunk = 5 float4 slots (4 data + 1 pad, 80B
// stride). Chunk bases 16B-aligned -> all smem traffic is LDS.128/STS.128,
// conflict-free in the scan phases (stride-80B covers all 32 banks per
// quarter-warp phase).
//
// r == 0.5f exactly for this module (log_r = inv_sigmoid(0.5) = 0), so u^r
// specializes to one MUFU.SQRT (runtime uniform check; __powf fallback kept).

#define T_LEN   4000
#define THREADS 256
#define CHUNK   16
#define NCHUNK  (T_LEN / CHUNK)   // 250
#define NVEC4   (T_LEN / 4)       // 1000
#define SLOT_STRIDE 5             // float4 slots per chunk
#define NSLOTS  (NCHUNK * SLOT_STRIDE)  // 1250 float4 = 20000 B
#define EPS     1e-6f

__device__ __forceinline__ float sqrt_approx(float x) {
    float y;
    asm("sqrt.approx.f32 %0, %1;" : "=f"(y) : "f"(x));
    return y;
}

__global__ __launch_bounds__(THREADS, 4)
void pcen_kernel(const float* __restrict__ E,
                 const float* __restrict__ log_alpha,
                 const float* __restrict__ log_delta,
                 const float* __restrict__ log_r,
                 const float* __restrict__ log_s,
                 float* __restrict__ out,
                 int C)
{
    __shared__ float4 buf4[NSLOTS];
    __shared__ float warp_sum[THREADS / 32];
    __shared__ float warp_pref[THREADS / 32];

    const int row = blockIdx.x;            // b*C + c
    const int c   = row % C;
    const float4* e4 = (const float4*)(E   + (size_t)row * T_LEN);
    float4*       o4 = (float4*)      (out + (size_t)row * T_LEN);

    const int tid  = threadIdx.x;
    const int lane = tid & 31;
    const int wid  = tid >> 5;

    // --- per-channel params (redundant per thread; cheap) ---
    const float s     = 1.0f / (1.0f + __expf(-__ldg(&log_s[c])));
    const float a     = 1.0f - s;
    const float alpha = 1.0f / (1.0f + __expf(-__ldg(&log_alpha[c])));
    const float delta = __logf(1.0f + __expf(__ldg(&log_delta[c])));
    const float r     = 1.0f / (1.0f + __expf(-__ldg(&log_r[c])));
    const float dr    = __powf(delta, r);

    // --- coalesced float4 load into padded smem ---
    // float4 j -> chunk j>>2, pos j&3 -> slot (j>>2)*5 + (j&3) = j + (j>>2)
    #pragma unroll 2
    for (int j = tid; j < NVEC4; j += THREADS) {
        buf4[j + (j >> 2)] = __ldg(&e4[j]);
    }
    __syncthreads();

    // --- pass 1: thread-local scan over its 16-chunk (LDS.128, conflict-free) ---
    float ev[CHUNK];
    float local = 0.0f;
    const int slot = tid * SLOT_STRIDE;
    if (tid < NCHUNK) {
        #pragma unroll
        for (int q = 0; q < 4; q++) {
            float4 v = buf4[slot + q];
            ev[4*q + 0] = v.x;
            ev[4*q + 1] = v.y;
            ev[4*q + 2] = v.z;
            ev[4*q + 3] = v.w;
        }
        #pragma unroll
        for (int k = 0; k < CHUNK; k++) {
            local = a * local + s * ev[k];
        }
    }

    // A = a^16 (chunk ratio)
    float A = a * a;          // a^2
    A = A * A;                // a^4
    A = A * A;                // a^8
    A = A * A;                // a^16

    // --- warp Hillis-Steele scan of p_i = A * p_{i-1} + local_i ---
    // Apow = A^lane built from the doubling w for free.
    float p = local;
    float w = A;              // A^(2^k)
    float Apow = 1.0f;        // A^lane
    #pragma unroll
    for (int d = 1; d < 32; d <<= 1) {
        float up = __shfl_up_sync(0xffffffffu, p, d);
        if (lane >= d) p += w * up;
        if (lane & d)  Apow *= w;
        w = w * w;
    }
    const float A32 = w;      // A^32

    // exclusive prefix within warp
    float pe = __shfl_up_sync(0xffffffffu, p, 1);
    if (lane == 0) pe = 0.0f;

    if (lane == 31) warp_sum[wid] = p;
    __syncthreads();

    // serial carry across the 8 warps (ratio A32), exclusive
    if (tid == 0) {
        float acc = 0.0f;
        #pragma unroll
        for (int j = 0; j < THREADS / 32; j++) {
            warp_pref[j] = acc;
            acc = A32 * acc + warp_sum[j];
        }
    }
    __syncthreads();

    // --- pass 2: recompute with true incoming state, apply PCEN math ---
    if (tid < NCHUNK) {
        float m = Apow * warp_pref[wid] + pe;   // M state before this chunk
        if (r == 0.5f) {
            #pragma unroll
            for (int k = 0; k < CHUNK; k++) {
                m = a * m + s * ev[k];
                float x  = EPS + m;
                float pw = __powf(x, -alpha);    // LG2+EX2
                float u  = ev[k] * pw + delta;
                ev[k]    = sqrt_approx(u) - dr;  // u^0.5: single MUFU.SQRT
            }
        } else {
            #pragma unroll
            for (int k = 0; k < CHUNK; k++) {
                m = a * m + s * ev[k];
                float x  = EPS + m;
                float pw = __powf(x, -alpha);
                float u  = ev[k] * pw + delta;
                ev[k]    = __powf(u, r) - dr;
            }
        }
        // write results back via STS.128 (conflict-free)
        #pragma unroll
        for (int q = 0; q < 4; q++) {
            float4 v;
            v.x = ev[4*q + 0];
            v.y = ev[4*q + 1];
            v.z = ev[4*q + 2];
            v.w = ev[4*q + 3];
            buf4[slot + q] = v;
        }
    }
    __syncthreads();

    // --- coalesced float4 store ---
    #pragma unroll 2
    for (int j = tid; j < NVEC4; j += THREADS) {
        o4[j] = buf4[j + (j >> 2)];
    }
}

extern "C" void kernel_launch(void* const* d_in, const int* in_sizes, int n_in,
                              void* d_out, int out_size)
{
    const float* E         = (const float*)d_in[0];
    const float* log_alpha = (const float*)d_in[1];
    const float* log_delta = (const float*)d_in[2];
    const float* log_r     = (const float*)d_in[3];
    const float* log_s     = (const float*)d_in[4];
    float*       out       = (float*)d_out;

    const int C    = in_sizes[1];
    const int rows = in_sizes[0] / T_LEN;   // B*C

    pcen_kernel<<<rows, THREADS>>>(E, log_alpha, log_delta, log_r, log_s, out, C);
}